// round 1
// baseline (speedup 1.0000x reference)
#include <cuda_runtime.h>
#include <math.h>

#define NN 50000
#define NE 640000
#define DD 128

// ---------------- scratch (no allocations allowed) ----------------
__device__ float g_h[(size_t)NN * DD];      // per-layer GEMM output
__device__ float g_o[(size_t)NN * DD];      // per-layer aggregation output
__device__ float g_dis_role[NN];            // deg counter -> rsqrt(deg)
__device__ float g_dis_norm[NN];

// ---------------- degree / norm ----------------
__global__ void k_init_deg(float* a, float* b, int n) {
    int i = blockIdx.x * blockDim.x + threadIdx.x;
    if (i < n) { a[i] = 1.0f; b[i] = 1.0f; }   // self-loop baked in
}

__global__ void k_count_deg(const int* __restrict__ dst, float* deg, int ne) {
    int i = blockIdx.x * blockDim.x + threadIdx.x;
    if (i < ne) atomicAdd(&deg[dst[i]], 1.0f);
}

__global__ void k_rsqrt2(float* a, float* b, int n) {
    int i = blockIdx.x * blockDim.x + threadIdx.x;
    if (i < n) { a[i] = rsqrtf(a[i]); b[i] = rsqrtf(b[i]); }
}

// ---------------- GEMM: H[M,128] = act(X[M,128]) @ W[128,128] ----------------
// 64-row x 128-col tile per 256-thread block; 4x8 outputs per thread.
template <bool RELU_IN>
__global__ void k_gemm128(const float* __restrict__ X, const float* __restrict__ W,
                          float* __restrict__ H, int M) {
    __shared__ float xs[16][68];    // [k][row], padded
    __shared__ float ws[16][132];   // [k][col], padded

    const int t = threadIdx.x;
    const int row0 = blockIdx.x * 64;
    const int tr = t >> 4;          // 0..15 -> rows tr*4..tr*4+3
    const int tc = t & 15;          // 0..15 -> cols tc*8..tc*8+7

    float acc[4][8];
#pragma unroll
    for (int i = 0; i < 4; i++)
#pragma unroll
        for (int j = 0; j < 8; j++) acc[i][j] = 0.0f;

    for (int k0 = 0; k0 < 128; k0 += 16) {
        // load X tile (64 rows x 16 k), one float4 per thread
        {
            int r = t >> 2;
            int kq = (t & 3) * 4;
            int rr = row0 + r; if (rr >= M) rr = M - 1;   // clamp (stores guarded)
            float4 v = *(const float4*)&X[(size_t)rr * DD + k0 + kq];
            if (RELU_IN) {
                v.x = fmaxf(v.x, 0.0f); v.y = fmaxf(v.y, 0.0f);
                v.z = fmaxf(v.z, 0.0f); v.w = fmaxf(v.w, 0.0f);
            }
            xs[kq + 0][r] = v.x; xs[kq + 1][r] = v.y;
            xs[kq + 2][r] = v.z; xs[kq + 3][r] = v.w;
        }
        // load W tile (16 k x 128 cols): 512 float4 slots, 2 per thread
#pragma unroll
        for (int s = t; s < 512; s += 256) {
            int k = s >> 5;
            int c4 = s & 31;
            float4 v = *(const float4*)&W[(size_t)(k0 + k) * DD + c4 * 4];
            ws[k][c4 * 4 + 0] = v.x; ws[k][c4 * 4 + 1] = v.y;
            ws[k][c4 * 4 + 2] = v.z; ws[k][c4 * 4 + 3] = v.w;
        }
        __syncthreads();

#pragma unroll
        for (int kk = 0; kk < 16; kk++) {
            float a[4], b[8];
#pragma unroll
            for (int i = 0; i < 4; i++) a[i] = xs[kk][tr * 4 + i];
#pragma unroll
            for (int j = 0; j < 8; j++) b[j] = ws[kk][tc * 8 + j];
#pragma unroll
            for (int i = 0; i < 4; i++)
#pragma unroll
                for (int j = 0; j < 8; j++) acc[i][j] = fmaf(a[i], b[j], acc[i][j]);
        }
        __syncthreads();
    }

#pragma unroll
    for (int i = 0; i < 4; i++) {
        int r = row0 + tr * 4 + i;
        if (r < M) {
            float4 v0 = make_float4(acc[i][0], acc[i][1], acc[i][2], acc[i][3]);
            float4 v1 = make_float4(acc[i][4], acc[i][5], acc[i][6], acc[i][7]);
            *(float4*)&H[(size_t)r * DD + tc * 8]     = v0;
            *(float4*)&H[(size_t)r * DD + tc * 8 + 4] = v1;
        }
    }
}

// ---------------- self-loop + bias init: out = h * dis^2 + b ----------------
__global__ void k_init_out(const float* __restrict__ h, const float* __restrict__ dis,
                           const float* __restrict__ bias, float* __restrict__ out, int n) {
    int idx = blockIdx.x * blockDim.x + threadIdx.x;   // over n*DD/4 float4s
    int total = n * (DD / 4);
    if (idx < total) {
        int node = idx >> 5;            // DD/4 = 32 float4 per row
        int c4 = (idx & 31) * 4;
        float s = dis[node];
        float inv = s * s;
        float4 v = *(const float4*)&h[(size_t)node * DD + c4];
        const float4 bb = *(const float4*)&bias[c4];
        v.x = v.x * inv + bb.x; v.y = v.y * inv + bb.y;
        v.z = v.z * inv + bb.z; v.w = v.w * inv + bb.w;
        *(float4*)&out[(size_t)node * DD + c4] = v;
    }
}

// ---------------- edge scatter: out[dst] += h[src] * dis[src]*dis[dst] ----------------
// One warp per edge; each lane handles 4 channels.
__global__ void k_scatter(const float* __restrict__ h, const float* __restrict__ dis,
                          const int* __restrict__ src, const int* __restrict__ dst,
                          float* __restrict__ out, int ne) {
    int w = (blockIdx.x * blockDim.x + threadIdx.x) >> 5;
    int lane = threadIdx.x & 31;
    if (w >= ne) return;
    int s = src[w];
    int d = dst[w];
    float norm = dis[s] * dis[d];
    float4 v = *(const float4*)&h[(size_t)s * DD + lane * 4];
    float* o = &out[(size_t)d * DD + lane * 4];
    atomicAdd(o + 0, v.x * norm);
    atomicAdd(o + 1, v.y * norm);
    atomicAdd(o + 2, v.z * norm);
    atomicAdd(o + 3, v.w * norm);
}

// ---------------- launch ----------------
static void run_layer(const float* X, const float* W, const float* b,
                      const float* dis, const int* src, const int* dst,
                      float* h, float* out, bool relu_in) {
    const int gemm_blocks = (NN + 63) / 64;
    if (relu_in)
        k_gemm128<true><<<gemm_blocks, 256>>>(X, W, h, NN);
    else
        k_gemm128<false><<<gemm_blocks, 256>>>(X, W, h, NN);

    k_init_out<<<(NN * (DD / 4) + 255) / 256, 256>>>(h, dis, b, out, NN);

    const long long threads = (long long)NE * 32;
    k_scatter<<<(int)((threads + 255) / 256), 256>>>(h, dis, src, dst, out, NE);
}

extern "C" void kernel_launch(void* const* d_in, const int* in_sizes, int n_in,
                              void* d_out, int out_size) {
    const float* x      = (const float*)d_in[0];
    const float* W_role = (const float*)d_in[1];
    const float* b_role = (const float*)d_in[2];
    const float* W2     = (const float*)d_in[3];
    const float* b2     = (const float*)d_in[4];
    const float* W1     = (const float*)d_in[5];
    const float* b1     = (const float*)d_in[6];
    const int* ei_norm  = (const int*)d_in[7];   // [2, NE]: row0 = src, row1 = dst
    const int* ei_role  = (const int*)d_in[8];

    float* h; float* o; float* dis_role; float* dis_norm;
    cudaGetSymbolAddress((void**)&h, g_h);
    cudaGetSymbolAddress((void**)&o, g_o);
    cudaGetSymbolAddress((void**)&dis_role, g_dis_role);
    cudaGetSymbolAddress((void**)&dis_norm, g_dis_norm);

    const int* src_norm = ei_norm;
    const int* dst_norm = ei_norm + NE;
    const int* src_role = ei_role;
    const int* dst_role = ei_role + NE;

    // degrees -> dis = rsqrt(indeg + 1)
    k_init_deg<<<(NN + 255) / 256, 256>>>(dis_role, dis_norm, NN);
    k_count_deg<<<(NE + 255) / 256, 256>>>(dst_role, dis_role, NE);
    k_count_deg<<<(NE + 255) / 256, 256>>>(dst_norm, dis_norm, NE);
    k_rsqrt2<<<(NN + 255) / 256, 256>>>(dis_role, dis_norm, NN);

    // layer 1: role graph, relu on output (applied as relu-on-input of layer 2)
    run_layer(x, W_role, b_role, dis_role, src_role, dst_role, h, o, /*relu_in=*/false);
    // layer 2: normal graph
    run_layer(o, W2, b2, dis_norm, src_norm, dst_norm, h, o, /*relu_in=*/true);
    // layer 3: normal graph, writes final output (no relu)
    run_layer(o, W1, b1, dis_norm, src_norm, dst_norm, h, (float*)d_out, /*relu_in=*/true);
}

// round 3
// speedup vs baseline: 1.8718x; 1.8718x over previous
#include <cuda_runtime.h>
#include <math.h>

#define NN 50000
#define NE 640000
#define DD 128

// ---------------- scratch (no allocations allowed) ----------------
__device__ float g_h[(size_t)NN * DD];      // per-layer GEMM output (pre-scaled by dis[row])
__device__ float g_o[(size_t)NN * DD];      // per-layer aggregation output
__device__ float g_dis_role[NN];
__device__ float g_dis_norm[NN];
__device__ int   g_cnt[NN];                 // per-graph temp: indegree counts
__device__ int   g_cur[NN];                 // per-graph temp: fill cursor
__device__ int   g_rp_role[NN + 1];         // CSR row pointers (by dst)
__device__ int   g_rp_norm[NN + 1];
__device__ int   g_col_role[NE];            // CSR column (src) lists
__device__ int   g_col_norm[NE];

// ---------------- CSR build ----------------
__global__ void k_zero(int* a, int n) {
    int i = blockIdx.x * blockDim.x + threadIdx.x;
    if (i < n) a[i] = 0;
}

__global__ void k_hist(const int* __restrict__ dst, int* __restrict__ cnt, int ne) {
    int i = blockIdx.x * blockDim.x + threadIdx.x;
    if (i < ne) atomicAdd(&cnt[dst[i]], 1);
}

// Single-block scan: rp[i+1] = prefix(cnt), cur[i] = exclusive prefix,
// dis[i] = rsqrt(cnt[i] + 1). Sequential 1024-wide chunks with carry.
__global__ void k_scan(const int* __restrict__ cnt, int* __restrict__ rp,
                       int* __restrict__ cur, float* __restrict__ dis, int n) {
    __shared__ int warp_sums[32];
    __shared__ int s_carry;
    const int t = threadIdx.x;
    if (t == 0) { s_carry = 0; rp[0] = 0; }
    __syncthreads();
    for (int base = 0; base < n; base += 1024) {
        int i = base + t;
        int v = (i < n) ? cnt[i] : 0;
        if (i < n) dis[i] = rsqrtf((float)(v + 1));
        // warp inclusive scan
        int x = v;
#pragma unroll
        for (int off = 1; off < 32; off <<= 1) {
            int y = __shfl_up_sync(0xffffffffu, x, off);
            if ((t & 31) >= off) x += y;
        }
        if ((t & 31) == 31) warp_sums[t >> 5] = x;
        __syncthreads();
        if (t < 32) {
            int ws = warp_sums[t];
#pragma unroll
            for (int off = 1; off < 32; off <<= 1) {
                int y = __shfl_up_sync(0xffffffffu, ws, off);
                if (t >= off) ws += y;
            }
            warp_sums[t] = ws;
        }
        __syncthreads();
        int incl = x + ((t >= 32) ? warp_sums[(t >> 5) - 1] : 0);
        int carry = s_carry;
        if (i < n) {
            rp[i + 1] = carry + incl;
            cur[i]    = carry + incl - v;
        }
        __syncthreads();
        if (t == 1023) s_carry = carry + incl;
        __syncthreads();
    }
}

__global__ void k_fill(const int* __restrict__ src, const int* __restrict__ dst,
                       int* __restrict__ cur, int* __restrict__ col, int ne) {
    int i = blockIdx.x * blockDim.x + threadIdx.x;
    if (i < ne) {
        int pos = atomicAdd(&cur[dst[i]], 1);
        col[pos] = src[i];
    }
}

// ---------------- GEMM: G[M,128] = (act(X[M,128]) @ W[128,128]) * dis[row] ----------------
template <bool RELU_IN>
__global__ void k_gemm128(const float* __restrict__ X, const float* __restrict__ W,
                          const float* __restrict__ dis, float* __restrict__ G, int M) {
    __shared__ float xs[16][68];    // [k][row], padded
    __shared__ float ws[16][132];   // [k][col], padded

    const int t = threadIdx.x;
    const int row0 = blockIdx.x * 64;
    const int tr = t >> 4;          // rows tr*4..tr*4+3
    const int tc = t & 15;          // cols tc*8..tc*8+7

    float acc[4][8];
#pragma unroll
    for (int i = 0; i < 4; i++)
#pragma unroll
        for (int j = 0; j < 8; j++) acc[i][j] = 0.0f;

    for (int k0 = 0; k0 < 128; k0 += 16) {
        {
            int r = t >> 2;
            int kq = (t & 3) * 4;
            int rr = row0 + r; if (rr >= M) rr = M - 1;
            float4 v = *(const float4*)&X[(size_t)rr * DD + k0 + kq];
            if (RELU_IN) {
                v.x = fmaxf(v.x, 0.0f); v.y = fmaxf(v.y, 0.0f);
                v.z = fmaxf(v.z, 0.0f); v.w = fmaxf(v.w, 0.0f);
            }
            xs[kq + 0][r] = v.x; xs[kq + 1][r] = v.y;
            xs[kq + 2][r] = v.z; xs[kq + 3][r] = v.w;
        }
#pragma unroll
        for (int s = t; s < 512; s += 256) {
            int k = s >> 5;
            int c4 = s & 31;
            float4 v = *(const float4*)&W[(size_t)(k0 + k) * DD + c4 * 4];
            ws[k][c4 * 4 + 0] = v.x; ws[k][c4 * 4 + 1] = v.y;
            ws[k][c4 * 4 + 2] = v.z; ws[k][c4 * 4 + 3] = v.w;
        }
        __syncthreads();

#pragma unroll
        for (int kk = 0; kk < 16; kk++) {
            float a[4], b[8];
#pragma unroll
            for (int i = 0; i < 4; i++) a[i] = xs[kk][tr * 4 + i];
#pragma unroll
            for (int j = 0; j < 8; j++) b[j] = ws[kk][tc * 8 + j];
#pragma unroll
            for (int i = 0; i < 4; i++)
#pragma unroll
                for (int j = 0; j < 8; j++) acc[i][j] = fmaf(a[i], b[j], acc[i][j]);
        }
        __syncthreads();
    }

#pragma unroll
    for (int i = 0; i < 4; i++) {
        int r = row0 + tr * 4 + i;
        if (r < M) {
            float s = dis[r];
            float4 v0 = make_float4(acc[i][0] * s, acc[i][1] * s, acc[i][2] * s, acc[i][3] * s);
            float4 v1 = make_float4(acc[i][4] * s, acc[i][5] * s, acc[i][6] * s, acc[i][7] * s);
            *(float4*)&G[(size_t)r * DD + tc * 8]     = v0;
            *(float4*)&G[(size_t)r * DD + tc * 8 + 4] = v1;
        }
    }
}

// ---------------- aggregation: out[i] = dis[i]*(g[i] + sum_{s in N(i)} g[s]) + b ----------------
// Warp per node; lane handles 4 channels (float4).
__global__ void k_aggregate(const float* __restrict__ g, const float* __restrict__ dis,
                            const float* __restrict__ bias, const int* __restrict__ rp,
                            const int* __restrict__ col, float* __restrict__ out, int n) {
    int node = (blockIdx.x * blockDim.x + threadIdx.x) >> 5;
    int lane = threadIdx.x & 31;
    if (node >= n) return;

    const int c = lane * 4;
    int beg = rp[node];
    int end = rp[node + 1];

    float4 a0 = *(const float4*)&g[(size_t)node * DD + c];   // self term
    float4 a1 = make_float4(0.f, 0.f, 0.f, 0.f);

    int e = beg;
    for (; e + 4 <= end; e += 4) {
        int s0 = __ldg(&col[e + 0]);
        int s1 = __ldg(&col[e + 1]);
        int s2 = __ldg(&col[e + 2]);
        int s3 = __ldg(&col[e + 3]);
        float4 v0 = *(const float4*)&g[(size_t)s0 * DD + c];
        float4 v1 = *(const float4*)&g[(size_t)s1 * DD + c];
        float4 v2 = *(const float4*)&g[(size_t)s2 * DD + c];
        float4 v3 = *(const float4*)&g[(size_t)s3 * DD + c];
        a0.x += v0.x; a0.y += v0.y; a0.z += v0.z; a0.w += v0.w;
        a1.x += v1.x; a1.y += v1.y; a1.z += v1.z; a1.w += v1.w;
        a0.x += v2.x; a0.y += v2.y; a0.z += v2.z; a0.w += v2.w;
        a1.x += v3.x; a1.y += v3.y; a1.z += v3.z; a1.w += v3.w;
    }
    for (; e < end; e++) {
        int s = __ldg(&col[e]);
        float4 v = *(const float4*)&g[(size_t)s * DD + c];
        a0.x += v.x; a0.y += v.y; a0.z += v.z; a0.w += v.w;
    }

    float di = dis[node];
    const float4 bb = *(const float4*)&bias[c];
    float4 r;
    r.x = (a0.x + a1.x) * di + bb.x;
    r.y = (a0.y + a1.y) * di + bb.y;
    r.z = (a0.z + a1.z) * di + bb.z;
    r.w = (a0.w + a1.w) * di + bb.w;
    *(float4*)&out[(size_t)node * DD + c] = r;
}

// ---------------- orchestration ----------------
static void build_csr(const int* src, const int* dst, int* cnt, int* cur,
                      int* rp, int* col, float* dis) {
    k_zero<<<(NN + 255) / 256, 256>>>(cnt, NN);
    k_hist<<<(NE + 255) / 256, 256>>>(dst, cnt, NE);
    k_scan<<<1, 1024>>>(cnt, rp, cur, dis, NN);
    k_fill<<<(NE + 255) / 256, 256>>>(src, dst, cur, col, NE);
}

static void run_layer(const float* X, const float* W, const float* b,
                      const float* dis, const int* rp, const int* col,
                      float* g, float* out, bool relu_in) {
    const int gemm_blocks = (NN + 63) / 64;
    if (relu_in)
        k_gemm128<true><<<gemm_blocks, 256>>>(X, W, dis, g, NN);
    else
        k_gemm128<false><<<gemm_blocks, 256>>>(X, W, dis, g, NN);

    const long long threads = (long long)NN * 32;
    k_aggregate<<<(int)((threads + 255) / 256), 256>>>(g, dis, b, rp, col, out, NN);
}

extern "C" void kernel_launch(void* const* d_in, const int* in_sizes, int n_in,
                              void* d_out, int out_size) {
    const float* x      = (const float*)d_in[0];
    const float* W_role = (const float*)d_in[1];
    const float* b_role = (const float*)d_in[2];
    const float* W2     = (const float*)d_in[3];
    const float* b2     = (const float*)d_in[4];
    const float* W1     = (const float*)d_in[5];
    const float* b1     = (const float*)d_in[6];
    const int* ei_norm  = (const int*)d_in[7];   // [2, NE]: row0 = src, row1 = dst
    const int* ei_role  = (const int*)d_in[8];

    float *h, *o, *dis_role, *dis_norm;
    int *cnt, *cur, *rp_role, *rp_norm, *col_role, *col_norm;
    cudaGetSymbolAddress((void**)&h, g_h);
    cudaGetSymbolAddress((void**)&o, g_o);
    cudaGetSymbolAddress((void**)&dis_role, g_dis_role);
    cudaGetSymbolAddress((void**)&dis_norm, g_dis_norm);
    cudaGetSymbolAddress((void**)&cnt, g_cnt);
    cudaGetSymbolAddress((void**)&cur, g_cur);
    cudaGetSymbolAddress((void**)&rp_role, g_rp_role);
    cudaGetSymbolAddress((void**)&rp_norm, g_rp_norm);
    cudaGetSymbolAddress((void**)&col_role, g_col_role);
    cudaGetSymbolAddress((void**)&col_norm, g_col_norm);

    const int* src_norm = ei_norm;
    const int* dst_norm = ei_norm + NE;
    const int* src_role = ei_role;
    const int* dst_role = ei_role + NE;

    build_csr(src_role, dst_role, cnt, cur, rp_role, col_role, dis_role);
    build_csr(src_norm, dst_norm, cnt, cur, rp_norm, col_norm, dis_norm);

    // layer 1: role graph
    run_layer(x, W_role, b_role, dis_role, rp_role, col_role, h, o, /*relu_in=*/false);
    // layer 2: normal graph (relu applied to layer-1 output on GEMM input)
    run_layer(o, W2, b2, dis_norm, rp_norm, col_norm, h, o, /*relu_in=*/true);
    // layer 3: normal graph, final output (no trailing relu)
    run_layer(o, W1, b1, dis_norm, rp_norm, col_norm, h, (float*)d_out, /*relu_in=*/true);
}

// round 8
// speedup vs baseline: 2.5406x; 1.3573x over previous
#include <cuda_runtime.h>
#include <math.h>
#include <cstdint>

#define NN 50000
#define NE 640000
#define DD 128

// ---------------- scratch (no allocations allowed) ----------------
__device__ float g_h[(size_t)NN * DD];      // per-layer GEMM output (pre-scaled by dis[row])
__device__ float g_o[(size_t)NN * DD];      // per-layer aggregation output
__device__ float g_wt[3 * DD * DD];         // transposed weights Wt[n][k] = W[k][n]
__device__ float g_dis_role[NN];
__device__ float g_dis_norm[NN];
__device__ int   g_cnt[NN];
__device__ int   g_cur[NN];
__device__ int   g_rp_role[NN + 1];
__device__ int   g_rp_norm[NN + 1];
__device__ int   g_col_role[NE];
__device__ int   g_col_norm[NE];

// ---------------- CSR build ----------------
__global__ void k_zero(int* a, int n) {
    int i = blockIdx.x * blockDim.x + threadIdx.x;
    if (i < n) a[i] = 0;
}

__global__ void k_hist(const int* __restrict__ dst, int* __restrict__ cnt, int ne) {
    int i = blockIdx.x * blockDim.x + threadIdx.x;
    if (i < ne) atomicAdd(&cnt[dst[i]], 1);
}

__global__ void k_scan(const int* __restrict__ cnt, int* __restrict__ rp,
                       int* __restrict__ cur, float* __restrict__ dis, int n) {
    __shared__ int warp_sums[32];
    __shared__ int s_carry;
    const int t = threadIdx.x;
    if (t == 0) { s_carry = 0; rp[0] = 0; }
    __syncthreads();
    for (int base = 0; base < n; base += 1024) {
        int i = base + t;
        int v = (i < n) ? cnt[i] : 0;
        if (i < n) dis[i] = rsqrtf((float)(v + 1));
        int x = v;
#pragma unroll
        for (int off = 1; off < 32; off <<= 1) {
            int y = __shfl_up_sync(0xffffffffu, x, off);
            if ((t & 31) >= off) x += y;
        }
        if ((t & 31) == 31) warp_sums[t >> 5] = x;
        __syncthreads();
        if (t < 32) {
            int ws = warp_sums[t];
#pragma unroll
            for (int off = 1; off < 32; off <<= 1) {
                int y = __shfl_up_sync(0xffffffffu, ws, off);
                if (t >= off) ws += y;
            }
            warp_sums[t] = ws;
        }
        __syncthreads();
        int incl = x + ((t >= 32) ? warp_sums[(t >> 5) - 1] : 0);
        int carry = s_carry;
        if (i < n) {
            rp[i + 1] = carry + incl;
            cur[i]    = carry + incl - v;
        }
        __syncthreads();
        if (t == 1023) s_carry = carry + incl;
        __syncthreads();
    }
}

__global__ void k_fill(const int* __restrict__ src, const int* __restrict__ dst,
                       int* __restrict__ cur, int* __restrict__ col, int ne) {
    int i = blockIdx.x * blockDim.x + threadIdx.x;
    if (i < ne) {
        int pos = atomicAdd(&cur[dst[i]], 1);
        col[pos] = src[i];
    }
}

// ---------------- weight transpose: Wt[n][k] = W[k][n] (3 matrices) ----------------
__global__ void k_transpose3(const float* __restrict__ W0, const float* __restrict__ W1,
                             const float* __restrict__ W2, float* __restrict__ Wt) {
    __shared__ float tile[32][33];
    int mat = blockIdx.z;
    const float* W = (mat == 0) ? W0 : (mat == 1) ? W1 : W2;
    float* O = Wt + (size_t)mat * DD * DD;
    int bx = blockIdx.x * 32, by = blockIdx.y * 32;
    int tx = threadIdx.x, ty = threadIdx.y;
#pragma unroll
    for (int j = 0; j < 32; j += 8)
        tile[ty + j][tx] = W[(size_t)(by + ty + j) * DD + bx + tx];
    __syncthreads();
#pragma unroll
    for (int j = 0; j < 32; j += 8)
        O[(size_t)(bx + ty + j) * DD + by + tx] = tile[tx][ty + j];
}

// ================= tensor-core tf32 GEMM (mma.sync, 3xTF32 compensated) =================
__device__ __forceinline__ float f2tf32(float x) {
    float r;
    asm("cvt.rna.tf32.f32 %0, %1;" : "=f"(r) : "f"(x));
    return r;
}

__device__ __forceinline__ void mma_m16n8k8(float c[4], const float a[4], float b0, float b1) {
    uint32_t a0 = __float_as_uint(a[0]), a1 = __float_as_uint(a[1]);
    uint32_t a2 = __float_as_uint(a[2]), a3 = __float_as_uint(a[3]);
    uint32_t B0 = __float_as_uint(b0),  B1 = __float_as_uint(b1);
    asm volatile(
        "mma.sync.aligned.m16n8k8.row.col.f32.tf32.tf32.f32 "
        "{%0,%1,%2,%3}, {%4,%5,%6,%7}, {%8,%9}, {%0,%1,%2,%3};"
        : "+f"(c[0]), "+f"(c[1]), "+f"(c[2]), "+f"(c[3])
        : "r"(a0), "r"(a1), "r"(a2), "r"(a3), "r"(B0), "r"(B1));
}

// Block: 256 threads / 8 warps. Block tile M=128, N=128 (full), K chunked by 64.
// Warp grid 4x2: warp_m = wid>>1 (32 rows each), warp_n = wid&1 (64 cols each).
// smem: a_hi/a_lo [128][68], b_hi/b_lo [128][68]  (stride 68 -> conflict-free frags)
#define GS 68
#define SMEM_GEMM (4 * 128 * GS * 4)

template <bool RELU_IN>
__global__ void __launch_bounds__(256, 1) k_gemm_mma(const float* __restrict__ X,
                                                     const float* __restrict__ Wt,
                                                     const float* __restrict__ dis,
                                                     float* __restrict__ G, int M) {
    extern __shared__ float sm[];
    float* a_hi = sm;
    float* a_lo = a_hi + 128 * GS;
    float* b_hi = a_lo + 128 * GS;
    float* b_lo = b_hi + 128 * GS;

    const int t = threadIdx.x;
    const int wid = t >> 5, lane = t & 31;
    const int gid = lane >> 2, tg = lane & 3;
    const int wm = wid >> 1, wn = wid & 1;
    const int row0 = blockIdx.x * 128;

    float c[2][8][4];
#pragma unroll
    for (int mi = 0; mi < 2; mi++)
#pragma unroll
        for (int ni = 0; ni < 8; ni++)
#pragma unroll
            for (int q = 0; q < 4; q++) c[mi][ni][q] = 0.0f;

    for (int kc = 0; kc < 2; kc++) {
        const int k0g = kc * 64;
        // load A chunk [128 rows x 64 k] with relu + hi/lo split
#pragma unroll
        for (int idx = t; idx < 2048; idx += 256) {
            int row = idx >> 4;
            int q = (idx & 15) * 4;
            int gr = row0 + row; if (gr >= M) gr = M - 1;
            float4 v = *(const float4*)&X[(size_t)gr * DD + k0g + q];
            if (RELU_IN) {
                v.x = fmaxf(v.x, 0.0f); v.y = fmaxf(v.y, 0.0f);
                v.z = fmaxf(v.z, 0.0f); v.w = fmaxf(v.w, 0.0f);
            }
            float* ph = &a_hi[row * GS + q];
            float* pl = &a_lo[row * GS + q];
            float h0 = f2tf32(v.x), h1 = f2tf32(v.y), h2 = f2tf32(v.z), h3 = f2tf32(v.w);
            ph[0] = h0; ph[1] = h1; ph[2] = h2; ph[3] = h3;
            pl[0] = f2tf32(v.x - h0); pl[1] = f2tf32(v.y - h1);
            pl[2] = f2tf32(v.z - h2); pl[3] = f2tf32(v.w - h3);
        }
        // load B chunk [128 n x 64 k] from Wt (already [n][k])
#pragma unroll
        for (int idx = t; idx < 2048; idx += 256) {
            int n = idx >> 4;
            int q = (idx & 15) * 4;
            float4 v = *(const float4*)&Wt[(size_t)n * DD + k0g + q];
            float* ph = &b_hi[n * GS + q];
            float* pl = &b_lo[n * GS + q];
            float h0 = f2tf32(v.x), h1 = f2tf32(v.y), h2 = f2tf32(v.z), h3 = f2tf32(v.w);
            ph[0] = h0; ph[1] = h1; ph[2] = h2; ph[3] = h3;
            pl[0] = f2tf32(v.x - h0); pl[1] = f2tf32(v.y - h1);
            pl[2] = f2tf32(v.z - h2); pl[3] = f2tf32(v.w - h3);
        }
        __syncthreads();

#pragma unroll
        for (int ks = 0; ks < 8; ks++) {
            const int k = ks * 8;
            // A fragments for both m16 tiles
            float ah[2][4], al[2][4];
#pragma unroll
            for (int mi = 0; mi < 2; mi++) {
                int r = wm * 32 + mi * 16 + gid;
                int base = r * GS + k + tg;
                ah[mi][0] = a_hi[base];
                ah[mi][1] = a_hi[base + 8 * GS];
                ah[mi][2] = a_hi[base + 4];
                ah[mi][3] = a_hi[base + 8 * GS + 4];
                al[mi][0] = a_lo[base];
                al[mi][1] = a_lo[base + 8 * GS];
                al[mi][2] = a_lo[base + 4];
                al[mi][3] = a_lo[base + 8 * GS + 4];
            }
#pragma unroll
            for (int ni = 0; ni < 8; ni++) {
                int n = wn * 64 + ni * 8 + gid;
                int bb = n * GS + k + tg;
                float bh0 = b_hi[bb], bh1 = b_hi[bb + 4];
                float bl0 = b_lo[bb], bl1 = b_lo[bb + 4];
#pragma unroll
                for (int mi = 0; mi < 2; mi++) {
                    mma_m16n8k8(c[mi][ni], ah[mi], bh0, bh1);   // hi*hi
                    mma_m16n8k8(c[mi][ni], ah[mi], bl0, bl1);   // hi*lo
                    mma_m16n8k8(c[mi][ni], al[mi], bh0, bh1);   // lo*hi
                }
            }
        }
        __syncthreads();
    }

    // epilogue: scale rows by dis and store
#pragma unroll
    for (int mi = 0; mi < 2; mi++) {
        int r0g = row0 + wm * 32 + mi * 16 + gid;
        int r1g = r0g + 8;
        float s0 = (r0g < M) ? dis[r0g] : 0.0f;
        float s1 = (r1g < M) ? dis[r1g] : 0.0f;
#pragma unroll
        for (int ni = 0; ni < 8; ni++) {
            int cg = wn * 64 + ni * 8 + tg * 2;
            if (r0g < M) {
                float2 v0 = make_float2(c[mi][ni][0] * s0, c[mi][ni][1] * s0);
                *(float2*)&G[(size_t)r0g * DD + cg] = v0;
            }
            if (r1g < M) {
                float2 v1 = make_float2(c[mi][ni][2] * s1, c[mi][ni][3] * s1);
                *(float2*)&G[(size_t)r1g * DD + cg] = v1;
            }
        }
    }
}

// ---------------- aggregation: out[i] = dis[i]*(g[i] + sum_{s in N(i)} g[s]) + b ----------------
__global__ void k_aggregate(const float* __restrict__ g, const float* __restrict__ dis,
                            const float* __restrict__ bias, const int* __restrict__ rp,
                            const int* __restrict__ col, float* __restrict__ out, int n) {
    int node = (blockIdx.x * blockDim.x + threadIdx.x) >> 5;
    int lane = threadIdx.x & 31;
    if (node >= n) return;

    const int c = lane * 4;
    int beg = rp[node];
    int end = rp[node + 1];

    float4 a0 = *(const float4*)&g[(size_t)node * DD + c];
    float4 a1 = make_float4(0.f, 0.f, 0.f, 0.f);

    int e = beg;
    for (; e + 4 <= end; e += 4) {
        int s0 = __ldg(&col[e + 0]);
        int s1 = __ldg(&col[e + 1]);
        int s2 = __ldg(&col[e + 2]);
        int s3 = __ldg(&col[e + 3]);
        float4 v0 = *(const float4*)&g[(size_t)s0 * DD + c];
        float4 v1 = *(const float4*)&g[(size_t)s1 * DD + c];
        float4 v2 = *(const float4*)&g[(size_t)s2 * DD + c];
        float4 v3 = *(const float4*)&g[(size_t)s3 * DD + c];
        a0.x += v0.x; a0.y += v0.y; a0.z += v0.z; a0.w += v0.w;
        a1.x += v1.x; a1.y += v1.y; a1.z += v1.z; a1.w += v1.w;
        a0.x += v2.x; a0.y += v2.y; a0.z += v2.z; a0.w += v2.w;
        a1.x += v3.x; a1.y += v3.y; a1.z += v3.z; a1.w += v3.w;
    }
    for (; e < end; e++) {
        int s = __ldg(&col[e]);
        float4 v = *(const float4*)&g[(size_t)s * DD + c];
        a0.x += v.x; a0.y += v.y; a0.z += v.z; a0.w += v.w;
    }

    float di = dis[node];
    const float4 bb = *(const float4*)&bias[c];
    float4 r;
    r.x = (a0.x + a1.x) * di + bb.x;
    r.y = (a0.y + a1.y) * di + bb.y;
    r.z = (a0.z + a1.z) * di + bb.z;
    r.w = (a0.w + a1.w) * di + bb.w;
    *(float4*)&out[(size_t)node * DD + c] = r;
}

// ---------------- orchestration ----------------
static void build_csr(const int* src, const int* dst, int* cnt, int* cur,
                      int* rp, int* col, float* dis) {
    k_zero<<<(NN + 255) / 256, 256>>>(cnt, NN);
    k_hist<<<(NE + 255) / 256, 256>>>(dst, cnt, NE);
    k_scan<<<1, 1024>>>(cnt, rp, cur, dis, NN);
    k_fill<<<(NE + 255) / 256, 256>>>(src, dst, cur, col, NE);
}

static void run_layer(const float* X, const float* Wt, const float* b,
                      const float* dis, const int* rp, const int* col,
                      float* g, float* out, bool relu_in) {
    const int gemm_blocks = (NN + 127) / 128;
    if (relu_in)
        k_gemm_mma<true><<<gemm_blocks, 256, SMEM_GEMM>>>(X, Wt, dis, g, NN);
    else
        k_gemm_mma<false><<<gemm_blocks, 256, SMEM_GEMM>>>(X, Wt, dis, g, NN);

    const long long threads = (long long)NN * 32;
    k_aggregate<<<(int)((threads + 255) / 256), 256>>>(g, dis, b, rp, col, out, NN);
}

extern "C" void kernel_launch(void* const* d_in, const int* in_sizes, int n_in,
                              void* d_out, int out_size) {
    const float* x      = (const float*)d_in[0];
    const float* W_role = (const float*)d_in[1];
    const float* b_role = (const float*)d_in[2];
    const float* W2     = (const float*)d_in[3];
    const float* b2     = (const float*)d_in[4];
    const float* W1     = (const float*)d_in[5];
    const float* b1     = (const float*)d_in[6];
    const int* ei_norm  = (const int*)d_in[7];
    const int* ei_role  = (const int*)d_in[8];

    float *h, *o, *wt, *dis_role, *dis_norm;
    int *cnt, *cur, *rp_role, *rp_norm, *col_role, *col_norm;
    cudaGetSymbolAddress((void**)&h, g_h);
    cudaGetSymbolAddress((void**)&o, g_o);
    cudaGetSymbolAddress((void**)&wt, g_wt);
    cudaGetSymbolAddress((void**)&dis_role, g_dis_role);
    cudaGetSymbolAddress((void**)&dis_norm, g_dis_norm);
    cudaGetSymbolAddress((void**)&cnt, g_cnt);
    cudaGetSymbolAddress((void**)&cur, g_cur);
    cudaGetSymbolAddress((void**)&rp_role, g_rp_role);
    cudaGetSymbolAddress((void**)&rp_norm, g_rp_norm);
    cudaGetSymbolAddress((void**)&col_role, g_col_role);
    cudaGetSymbolAddress((void**)&col_norm, g_col_norm);

    static bool attr_set = false;
    if (!attr_set) {
        cudaFuncSetAttribute(k_gemm_mma<true>,  cudaFuncAttributeMaxDynamicSharedMemorySize, SMEM_GEMM);
        cudaFuncSetAttribute(k_gemm_mma<false>, cudaFuncAttributeMaxDynamicSharedMemorySize, SMEM_GEMM);
        attr_set = true;
    }

    const int* src_norm = ei_norm;
    const int* dst_norm = ei_norm + NE;
    const int* src_role = ei_role;
    const int* dst_role = ei_role + NE;

    // transposed weights: order = [W_role, W2, W1]
    {
        dim3 tb(32, 8), tg(4, 4, 3);
        k_transpose3<<<tg, tb>>>(W_role, W2, W1, wt);
    }

    build_csr(src_role, dst_role, cnt, cur, rp_role, col_role, dis_role);
    build_csr(src_norm, dst_norm, cnt, cur, rp_norm, col_norm, dis_norm);

    // layer 1: role graph
    run_layer(x, wt + 0 * DD * DD, b_role, dis_role, rp_role, col_role, h, o, /*relu_in=*/false);
    // layer 2: normal graph (relu on layer-1 output applied at GEMM input)
    run_layer(o, wt + 1 * DD * DD, b2, dis_norm, rp_norm, col_norm, h, o, /*relu_in=*/true);
    // layer 3: normal graph, final output
    run_layer(o, wt + 2 * DD * DD, b1, dis_norm, rp_norm, col_norm, h, (float*)d_out, /*relu_in=*/true);
}

// round 10
// speedup vs baseline: 3.3163x; 1.3053x over previous
#include <cuda_runtime.h>
#include <math.h>
#include <cstdint>

#define NN 50000
#define NE 640000
#define DD 128
#define SCAN_B 1024
#define SCAN_NB ((NN + SCAN_B - 1) / SCAN_B)   // 49

// ---------------- scratch (no allocations allowed) ----------------
__device__ float g_h[(size_t)NN * DD];      // per-layer GEMM output (pre-scaled by dis[row])
__device__ float g_o[(size_t)NN * DD];      // per-layer aggregation output
__device__ float g_wt[3 * DD * DD];         // transposed weights Wt[n][k] = W[k][n]
__device__ float g_dis_role[NN];
__device__ float g_dis_norm[NN];
__device__ int   g_cnt[NN];
__device__ int   g_cur[NN];
__device__ int   g_bsum[SCAN_NB];
__device__ int   g_boff[SCAN_NB];
__device__ int   g_rp_role[NN + 1];
__device__ int   g_rp_norm[NN + 1];
__device__ int   g_col_role[NE];
__device__ int   g_col_norm[NE];

// ---------------- CSR build ----------------
__global__ void k_zero(int* a, int n) {
    int i = blockIdx.x * blockDim.x + threadIdx.x;
    if (i < n) a[i] = 0;
}

__global__ void k_hist(const int* __restrict__ dst, int* __restrict__ cnt, int ne) {
    int i = blockIdx.x * blockDim.x + threadIdx.x;
    if (i < ne) atomicAdd(&cnt[dst[i]], 1);
}

// Phase 1: per-block inclusive scan; writes block-local rp/cur, dis, and block sums.
__global__ void k_scan1(const int* __restrict__ cnt, int* __restrict__ rp,
                        int* __restrict__ cur, float* __restrict__ dis,
                        int* __restrict__ bsum, int n) {
    __shared__ int warp_sums[32];
    const int t = threadIdx.x;
    const int i = blockIdx.x * SCAN_B + t;
    int v = (i < n) ? cnt[i] : 0;
    if (i < n) dis[i] = rsqrtf((float)(v + 1));
    int x = v;
#pragma unroll
    for (int off = 1; off < 32; off <<= 1) {
        int y = __shfl_up_sync(0xffffffffu, x, off);
        if ((t & 31) >= off) x += y;
    }
    if ((t & 31) == 31) warp_sums[t >> 5] = x;
    __syncthreads();
    if (t < 32) {
        int ws = warp_sums[t];
#pragma unroll
        for (int off = 1; off < 32; off <<= 1) {
            int y = __shfl_up_sync(0xffffffffu, ws, off);
            if (t >= off) ws += y;
        }
        warp_sums[t] = ws;
    }
    __syncthreads();
    int incl = x + ((t >= 32) ? warp_sums[(t >> 5) - 1] : 0);
    if (i < n) {
        rp[i + 1] = incl;          // block-local; offset added in phase 3
        cur[i]    = incl - v;
    }
    if (t == SCAN_B - 1) bsum[blockIdx.x] = incl;
    if (i == 0) rp[0] = 0;
}

// Phase 2: exclusive scan of the (<=64) block sums in one warp-ish block.
__global__ void k_scan2(const int* __restrict__ bsum, int* __restrict__ boff, int nb) {
    const int t = threadIdx.x;   // 64 threads
    int v = (t < nb) ? bsum[t] : 0;
    int x = v;
#pragma unroll
    for (int off = 1; off < 32; off <<= 1) {
        int y = __shfl_up_sync(0xffffffffu, x, off);
        if ((t & 31) >= off) x += y;
    }
    __shared__ int w0;
    if (t == 31) w0 = x;
    __syncthreads();
    if (t >= 32) x += w0;
    if (t < nb) boff[t] = x - v;   // exclusive
}

// Phase 3: add block offsets.
__global__ void k_scan3(int* __restrict__ rp, int* __restrict__ cur,
                        const int* __restrict__ boff, int n) {
    const int i = blockIdx.x * SCAN_B + threadIdx.x;
    if (i < n) {
        int o = boff[blockIdx.x];
        rp[i + 1] += o;
        cur[i]    += o;
    }
}

__global__ void k_fill(const int* __restrict__ src, const int* __restrict__ dst,
                       int* __restrict__ cur, int* __restrict__ col, int ne) {
    int i = blockIdx.x * blockDim.x + threadIdx.x;
    if (i < ne) {
        int pos = atomicAdd(&cur[dst[i]], 1);
        col[pos] = src[i];
    }
}

// ---------------- weight transpose: Wt[n][k] = W[k][n] (3 matrices) ----------------
__global__ void k_transpose3(const float* __restrict__ W0, const float* __restrict__ W1,
                             const float* __restrict__ W2, float* __restrict__ Wt) {
    __shared__ float tile[32][33];
    int mat = blockIdx.z;
    const float* W = (mat == 0) ? W0 : (mat == 1) ? W1 : W2;
    float* O = Wt + (size_t)mat * DD * DD;
    int bx = blockIdx.x * 32, by = blockIdx.y * 32;
    int tx = threadIdx.x, ty = threadIdx.y;
#pragma unroll
    for (int j = 0; j < 32; j += 8)
        tile[ty + j][tx] = W[(size_t)(by + ty + j) * DD + bx + tx];
    __syncthreads();
#pragma unroll
    for (int j = 0; j < 32; j += 8)
        O[(size_t)(bx + ty + j) * DD + by + tx] = tile[tx][ty + j];
}

// ================= tensor-core tf32 GEMM (mma.sync, 3xTF32 compensated) =================
__device__ __forceinline__ float f2tf32(float x) {
    float r;
    asm("cvt.rna.tf32.f32 %0, %1;" : "=f"(r) : "f"(x));
    return r;
}

__device__ __forceinline__ void mma_m16n8k8(float c[4], const float a[4], float b0, float b1) {
    uint32_t a0 = __float_as_uint(a[0]), a1 = __float_as_uint(a[1]);
    uint32_t a2 = __float_as_uint(a[2]), a3 = __float_as_uint(a[3]);
    uint32_t B0 = __float_as_uint(b0),  B1 = __float_as_uint(b1);
    asm volatile(
        "mma.sync.aligned.m16n8k8.row.col.f32.tf32.tf32.f32 "
        "{%0,%1,%2,%3}, {%4,%5,%6,%7}, {%8,%9}, {%0,%1,%2,%3};"
        : "+f"(c[0]), "+f"(c[1]), "+f"(c[2]), "+f"(c[3])
        : "r"(a0), "r"(a1), "r"(a2), "r"(a3), "r"(B0), "r"(B1));
}

// Block: 256 threads / 8 warps. Block tile M=128, N=128 (full), K chunked by 64.
#define GS 68
#define SMEM_GEMM (4 * 128 * GS * 4)

template <bool RELU_IN>
__global__ void __launch_bounds__(256, 1) k_gemm_mma(const float* __restrict__ X,
                                                     const float* __restrict__ Wt,
                                                     const float* __restrict__ dis,
                                                     float* __restrict__ G, int M) {
    extern __shared__ float sm[];
    float* a_hi = sm;
    float* a_lo = a_hi + 128 * GS;
    float* b_hi = a_lo + 128 * GS;
    float* b_lo = b_hi + 128 * GS;

    const int t = threadIdx.x;
    const int wid = t >> 5, lane = t & 31;
    const int gid = lane >> 2, tg = lane & 3;
    const int wm = wid >> 1, wn = wid & 1;
    const int row0 = blockIdx.x * 128;

    float c[2][8][4];
#pragma unroll
    for (int mi = 0; mi < 2; mi++)
#pragma unroll
        for (int ni = 0; ni < 8; ni++)
#pragma unroll
            for (int q = 0; q < 4; q++) c[mi][ni][q] = 0.0f;

    for (int kc = 0; kc < 2; kc++) {
        const int k0g = kc * 64;
#pragma unroll
        for (int idx = t; idx < 2048; idx += 256) {
            int row = idx >> 4;
            int q = (idx & 15) * 4;
            int gr = row0 + row; if (gr >= M) gr = M - 1;
            float4 v = *(const float4*)&X[(size_t)gr * DD + k0g + q];
            if (RELU_IN) {
                v.x = fmaxf(v.x, 0.0f); v.y = fmaxf(v.y, 0.0f);
                v.z = fmaxf(v.z, 0.0f); v.w = fmaxf(v.w, 0.0f);
            }
            float* ph = &a_hi[row * GS + q];
            float* pl = &a_lo[row * GS + q];
            float h0 = f2tf32(v.x), h1 = f2tf32(v.y), h2 = f2tf32(v.z), h3 = f2tf32(v.w);
            ph[0] = h0; ph[1] = h1; ph[2] = h2; ph[3] = h3;
            pl[0] = f2tf32(v.x - h0); pl[1] = f2tf32(v.y - h1);
            pl[2] = f2tf32(v.z - h2); pl[3] = f2tf32(v.w - h3);
        }
#pragma unroll
        for (int idx = t; idx < 2048; idx += 256) {
            int n = idx >> 4;
            int q = (idx & 15) * 4;
            float4 v = *(const float4*)&Wt[(size_t)n * DD + k0g + q];
            float* ph = &b_hi[n * GS + q];
            float* pl = &b_lo[n * GS + q];
            float h0 = f2tf32(v.x), h1 = f2tf32(v.y), h2 = f2tf32(v.z), h3 = f2tf32(v.w);
            ph[0] = h0; ph[1] = h1; ph[2] = h2; ph[3] = h3;
            pl[0] = f2tf32(v.x - h0); pl[1] = f2tf32(v.y - h1);
            pl[2] = f2tf32(v.z - h2); pl[3] = f2tf32(v.w - h3);
        }
        __syncthreads();

#pragma unroll
        for (int ks = 0; ks < 8; ks++) {
            const int k = ks * 8;
            float ah[2][4], al[2][4];
#pragma unroll
            for (int mi = 0; mi < 2; mi++) {
                int r = wm * 32 + mi * 16 + gid;
                int base = r * GS + k + tg;
                ah[mi][0] = a_hi[base];
                ah[mi][1] = a_hi[base + 8 * GS];
                ah[mi][2] = a_hi[base + 4];
                ah[mi][3] = a_hi[base + 8 * GS + 4];
                al[mi][0] = a_lo[base];
                al[mi][1] = a_lo[base + 8 * GS];
                al[mi][2] = a_lo[base + 4];
                al[mi][3] = a_lo[base + 8 * GS + 4];
            }
#pragma unroll
            for (int ni = 0; ni < 8; ni++) {
                int n = wn * 64 + ni * 8 + gid;
                int bb = n * GS + k + tg;
                float bh0 = b_hi[bb], bh1 = b_hi[bb + 4];
                float bl0 = b_lo[bb], bl1 = b_lo[bb + 4];
#pragma unroll
                for (int mi = 0; mi < 2; mi++) {
                    mma_m16n8k8(c[mi][ni], ah[mi], bh0, bh1);
                    mma_m16n8k8(c[mi][ni], ah[mi], bl0, bl1);
                    mma_m16n8k8(c[mi][ni], al[mi], bh0, bh1);
                }
            }
        }
        __syncthreads();
    }

#pragma unroll
    for (int mi = 0; mi < 2; mi++) {
        int r0g = row0 + wm * 32 + mi * 16 + gid;
        int r1g = r0g + 8;
        float s0 = (r0g < M) ? dis[r0g] : 0.0f;
        float s1 = (r1g < M) ? dis[r1g] : 0.0f;
#pragma unroll
        for (int ni = 0; ni < 8; ni++) {
            int cg = wn * 64 + ni * 8 + tg * 2;
            if (r0g < M) {
                float2 v0 = make_float2(c[mi][ni][0] * s0, c[mi][ni][1] * s0);
                *(float2*)&G[(size_t)r0g * DD + cg] = v0;
            }
            if (r1g < M) {
                float2 v1 = make_float2(c[mi][ni][2] * s1, c[mi][ni][3] * s1);
                *(float2*)&G[(size_t)r1g * DD + cg] = v1;
            }
        }
    }
}

// ---------------- aggregation: out[i] = dis[i]*(g[i] + sum_{s in N(i)} g[s]) + b ----------------
__global__ void k_aggregate(const float* __restrict__ g, const float* __restrict__ dis,
                            const float* __restrict__ bias, const int* __restrict__ rp,
                            const int* __restrict__ col, float* __restrict__ out, int n) {
    int node = (blockIdx.x * blockDim.x + threadIdx.x) >> 5;
    int lane = threadIdx.x & 31;
    if (node >= n) return;

    const int c = lane * 4;
    int beg = rp[node];
    int end = rp[node + 1];

    float4 a0 = *(const float4*)&g[(size_t)node * DD + c];
    float4 a1 = make_float4(0.f, 0.f, 0.f, 0.f);

    int e = beg;
    for (; e + 4 <= end; e += 4) {
        int s0 = __ldg(&col[e + 0]);
        int s1 = __ldg(&col[e + 1]);
        int s2 = __ldg(&col[e + 2]);
        int s3 = __ldg(&col[e + 3]);
        float4 v0 = *(const float4*)&g[(size_t)s0 * DD + c];
        float4 v1 = *(const float4*)&g[(size_t)s1 * DD + c];
        float4 v2 = *(const float4*)&g[(size_t)s2 * DD + c];
        float4 v3 = *(const float4*)&g[(size_t)s3 * DD + c];
        a0.x += v0.x; a0.y += v0.y; a0.z += v0.z; a0.w += v0.w;
        a1.x += v1.x; a1.y += v1.y; a1.z += v1.z; a1.w += v1.w;
        a0.x += v2.x; a0.y += v2.y; a0.z += v2.z; a0.w += v2.w;
        a1.x += v3.x; a1.y += v3.y; a1.z += v3.z; a1.w += v3.w;
    }
    for (; e < end; e++) {
        int s = __ldg(&col[e]);
        float4 v = *(const float4*)&g[(size_t)s * DD + c];
        a0.x += v.x; a0.y += v.y; a0.z += v.z; a0.w += v.w;
    }

    float di = dis[node];
    const float4 bb = *(const float4*)&bias[c];
    float4 r;
    r.x = (a0.x + a1.x) * di + bb.x;
    r.y = (a0.y + a1.y) * di + bb.y;
    r.z = (a0.z + a1.z) * di + bb.z;
    r.w = (a0.w + a1.w) * di + bb.w;
    *(float4*)&out[(size_t)node * DD + c] = r;
}

// ---------------- orchestration ----------------
static void build_csr(const int* src, const int* dst, int* cnt, int* cur,
                      int* bsum, int* boff, int* rp, int* col, float* dis) {
    k_zero<<<(NN + 255) / 256, 256>>>(cnt, NN);
    k_hist<<<(NE + 255) / 256, 256>>>(dst, cnt, NE);
    k_scan1<<<SCAN_NB, SCAN_B>>>(cnt, rp, cur, dis, bsum, NN);
    k_scan2<<<1, 64>>>(bsum, boff, SCAN_NB);
    k_scan3<<<SCAN_NB, SCAN_B>>>(rp, cur, boff, NN);
    k_fill<<<(NE + 255) / 256, 256>>>(src, dst, cur, col, NE);
}

static void run_layer(const float* X, const float* Wt, const float* b,
                      const float* dis, const int* rp, const int* col,
                      float* g, float* out, bool relu_in) {
    const int gemm_blocks = (NN + 127) / 128;
    if (relu_in)
        k_gemm_mma<true><<<gemm_blocks, 256, SMEM_GEMM>>>(X, Wt, dis, g, NN);
    else
        k_gemm_mma<false><<<gemm_blocks, 256, SMEM_GEMM>>>(X, Wt, dis, g, NN);

    const long long threads = (long long)NN * 32;
    k_aggregate<<<(int)((threads + 255) / 256), 256>>>(g, dis, b, rp, col, out, NN);
}

extern "C" void kernel_launch(void* const* d_in, const int* in_sizes, int n_in,
                              void* d_out, int out_size) {
    const float* x      = (const float*)d_in[0];
    const float* W_role = (const float*)d_in[1];
    const float* b_role = (const float*)d_in[2];
    const float* W2     = (const float*)d_in[3];
    const float* b2     = (const float*)d_in[4];
    const float* W1     = (const float*)d_in[5];
    const float* b1     = (const float*)d_in[6];
    const int* ei_norm  = (const int*)d_in[7];
    const int* ei_role  = (const int*)d_in[8];

    float *h, *o, *wt, *dis_role, *dis_norm;
    int *cnt, *cur, *bsum, *boff, *rp_role, *rp_norm, *col_role, *col_norm;
    cudaGetSymbolAddress((void**)&h, g_h);
    cudaGetSymbolAddress((void**)&o, g_o);
    cudaGetSymbolAddress((void**)&wt, g_wt);
    cudaGetSymbolAddress((void**)&dis_role, g_dis_role);
    cudaGetSymbolAddress((void**)&dis_norm, g_dis_norm);
    cudaGetSymbolAddress((void**)&cnt, g_cnt);
    cudaGetSymbolAddress((void**)&cur, g_cur);
    cudaGetSymbolAddress((void**)&bsum, g_bsum);
    cudaGetSymbolAddress((void**)&boff, g_boff);
    cudaGetSymbolAddress((void**)&rp_role, g_rp_role);
    cudaGetSymbolAddress((void**)&rp_norm, g_rp_norm);
    cudaGetSymbolAddress((void**)&col_role, g_col_role);
    cudaGetSymbolAddress((void**)&col_norm, g_col_norm);

    static bool attr_set = false;
    if (!attr_set) {
        cudaFuncSetAttribute(k_gemm_mma<true>,  cudaFuncAttributeMaxDynamicSharedMemorySize, SMEM_GEMM);
        cudaFuncSetAttribute(k_gemm_mma<false>, cudaFuncAttributeMaxDynamicSharedMemorySize, SMEM_GEMM);
        attr_set = true;
    }

    const int* src_norm = ei_norm;
    const int* dst_norm = ei_norm + NE;
    const int* src_role = ei_role;
    const int* dst_role = ei_role + NE;

    {
        dim3 tb(32, 8), tg(4, 4, 3);
        k_transpose3<<<tg, tb>>>(W_role, W2, W1, wt);
    }

    build_csr(src_role, dst_role, cnt, cur, bsum, boff, rp_role, col_role, dis_role);
    build_csr(src_norm, dst_norm, cnt, cur, bsum, boff, rp_norm, col_norm, dis_norm);

    // layer 1: role graph
    run_layer(x, wt + 0 * DD * DD, b_role, dis_role, rp_role, col_role, h, o, /*relu_in=*/false);
    // layer 2: normal graph (relu on layer-1 output applied at GEMM input)
    run_layer(o, wt + 1 * DD * DD, b2, dis_norm, rp_norm, col_norm, h, o, /*relu_in=*/true);
    // layer 3: normal graph, final output
    run_layer(o, wt + 2 * DD * DD, b1, dis_norm, rp_norm, col_norm, h, (float*)d_out, /*relu_in=*/true);
}

// round 11
// speedup vs baseline: 3.5376x; 1.0668x over previous
#include <cuda_runtime.h>
#include <cuda_bf16.h>
#include <math.h>
#include <cstdint>

#define NN 50000
#define NE 640000
#define DD 128
#define SCAN_B 1024
#define SCAN_NB ((NN + SCAN_B - 1) / SCAN_B)   // 49

// ---------------- scratch (no allocations allowed) ----------------
__device__ float g_h[(size_t)NN * DD];      // per-layer GEMM output (pre-scaled by dis[row])
__device__ float g_o[(size_t)NN * DD];      // per-layer aggregation output
__device__ __align__(16) uint16_t g_wthi[3 * DD * DD];  // Wt hi bf16 (Wt[n][k] = W[k][n])
__device__ __align__(16) uint16_t g_wtlo[3 * DD * DD];  // Wt lo bf16
__device__ float g_dis_role[NN];
__device__ float g_dis_norm[NN];
__device__ int   g_cnt[2 * NN];
__device__ int   g_cur[2 * NN];
__device__ int   g_bsum[2 * SCAN_NB];
__device__ int   g_boff[2 * SCAN_NB];
__device__ int   g_rp_role[NN + 1];
__device__ int   g_rp_norm[NN + 1];
__device__ int   g_col_role[NE];
__device__ int   g_col_norm[NE];

// ---------------- CSR build (both graphs in one pass, graph = blockIdx.y) ----------------
__global__ void k_zero2(int* a, int n) {
    int i = blockIdx.x * blockDim.x + threadIdx.x;
    if (i < n) a[i] = 0;
}

__global__ void k_hist2(const int* __restrict__ dst_role, const int* __restrict__ dst_norm,
                        int* __restrict__ cnt) {
    int e = blockIdx.x * blockDim.x + threadIdx.x;
    if (e < NE) {
        int g = blockIdx.y;
        const int* d = g ? dst_norm : dst_role;
        atomicAdd(&cnt[g * NN + d[e]], 1);
    }
}

__global__ void k_scan1(const int* __restrict__ cnt, int* __restrict__ rp0, int* __restrict__ rp1,
                        int* __restrict__ cur, float* __restrict__ dis0, float* __restrict__ dis1,
                        int* __restrict__ bsum) {
    __shared__ int warp_sums[32];
    const int g = blockIdx.y;
    const int* c = cnt + g * NN;
    int* rp = g ? rp1 : rp0;
    float* dis = g ? dis1 : dis0;
    int* curg = cur + g * NN;
    const int t = threadIdx.x;
    const int i = blockIdx.x * SCAN_B + t;
    int v = (i < NN) ? c[i] : 0;
    if (i < NN) dis[i] = rsqrtf((float)(v + 1));
    int x = v;
#pragma unroll
    for (int off = 1; off < 32; off <<= 1) {
        int y = __shfl_up_sync(0xffffffffu, x, off);
        if ((t & 31) >= off) x += y;
    }
    if ((t & 31) == 31) warp_sums[t >> 5] = x;
    __syncthreads();
    if (t < 32) {
        int ws = warp_sums[t];
#pragma unroll
        for (int off = 1; off < 32; off <<= 1) {
            int y = __shfl_up_sync(0xffffffffu, ws, off);
            if (t >= off) ws += y;
        }
        warp_sums[t] = ws;
    }
    __syncthreads();
    int incl = x + ((t >= 32) ? warp_sums[(t >> 5) - 1] : 0);
    if (i < NN) {
        rp[i + 1] = incl;          // block-local; offset added in phase 3
        curg[i]   = incl - v;
    }
    if (t == SCAN_B - 1) bsum[g * SCAN_NB + blockIdx.x] = incl;
    if (i == 0) rp[0] = 0;
}

__global__ void k_scan2(const int* __restrict__ bsum, int* __restrict__ boff) {
    const int g = blockIdx.x;
    const int t = threadIdx.x;   // 64 threads
    int v = (t < SCAN_NB) ? bsum[g * SCAN_NB + t] : 0;
    int x = v;
#pragma unroll
    for (int off = 1; off < 32; off <<= 1) {
        int y = __shfl_up_sync(0xffffffffu, x, off);
        if ((t & 31) >= off) x += y;
    }
    __shared__ int w0;
    if (t == 31) w0 = x;
    __syncthreads();
    if (t >= 32) x += w0;
    if (t < SCAN_NB) boff[g * SCAN_NB + t] = x - v;   // exclusive
}

__global__ void k_scan3(int* __restrict__ rp0, int* __restrict__ rp1, int* __restrict__ cur,
                        const int* __restrict__ boff) {
    const int g = blockIdx.y;
    int* rp = g ? rp1 : rp0;
    const int i = blockIdx.x * SCAN_B + threadIdx.x;
    if (i < NN) {
        int o = boff[g * SCAN_NB + blockIdx.x];
        rp[i + 1] += o;
        cur[g * NN + i] += o;
    }
}

__global__ void k_fill2(const int* __restrict__ src_role, const int* __restrict__ dst_role,
                        const int* __restrict__ src_norm, const int* __restrict__ dst_norm,
                        int* __restrict__ cur, int* __restrict__ col_role, int* __restrict__ col_norm) {
    int e = blockIdx.x * blockDim.x + threadIdx.x;
    if (e < NE) {
        int g = blockIdx.y;
        const int* s = g ? src_norm : src_role;
        const int* d = g ? dst_norm : dst_role;
        int* col = g ? col_norm : col_role;
        int pos = atomicAdd(&cur[g * NN + d[e]], 1);
        col[pos] = s[e];
    }
}

// ---------------- weight transpose + bf16 hi/lo split ----------------
__global__ void k_transpose3(const float* __restrict__ W0, const float* __restrict__ W1,
                             const float* __restrict__ W2,
                             uint16_t* __restrict__ WH, uint16_t* __restrict__ WL) {
    __shared__ float tile[32][33];
    int mat = blockIdx.z;
    const float* W = (mat == 0) ? W0 : (mat == 1) ? W1 : W2;
    uint16_t* OH = WH + (size_t)mat * DD * DD;
    uint16_t* OL = WL + (size_t)mat * DD * DD;
    int bx = blockIdx.x * 32, by = blockIdx.y * 32;
    int tx = threadIdx.x, ty = threadIdx.y;
#pragma unroll
    for (int j = 0; j < 32; j += 8)
        tile[ty + j][tx] = W[(size_t)(by + ty + j) * DD + bx + tx];
    __syncthreads();
#pragma unroll
    for (int j = 0; j < 32; j += 8) {
        float v = tile[tx][ty + j];
        __nv_bfloat16 h = __float2bfloat16_rn(v);
        __nv_bfloat16 l = __float2bfloat16_rn(v - __bfloat162float(h));
        size_t o = (size_t)(bx + ty + j) * DD + by + tx;
        OH[o] = __bfloat16_as_ushort(h);
        OL[o] = __bfloat16_as_ushort(l);
    }
}

// ================= bf16 split GEMM (mma.sync m16n8k16 + ldmatrix) =================
// G[M,128] = (act(X[M,128]) @ W) * dis[row], via hi*hi + hi*lo + lo*hi
__device__ __forceinline__ uint32_t smem_u32(const void* p) {
    uint32_t a;
    asm("{ .reg .u64 t; cvta.to.shared.u64 t, %1; cvt.u32.u64 %0, t; }" : "=r"(a) : "l"(p));
    return a;
}
__device__ __forceinline__ void ldsm4(uint32_t r[4], uint32_t a) {
    asm volatile("ldmatrix.sync.aligned.m8n8.x4.shared.b16 {%0,%1,%2,%3}, [%4];"
                 : "=r"(r[0]), "=r"(r[1]), "=r"(r[2]), "=r"(r[3]) : "r"(a));
}
__device__ __forceinline__ void mma_bf16(float c[4], const uint32_t a[4], uint32_t b0, uint32_t b1) {
    asm volatile("mma.sync.aligned.m16n8k16.row.col.f32.bf16.bf16.f32 "
                 "{%0,%1,%2,%3}, {%4,%5,%6,%7}, {%8,%9}, {%0,%1,%2,%3};"
                 : "+f"(c[0]), "+f"(c[1]), "+f"(c[2]), "+f"(c[3])
                 : "r"(a[0]), "r"(a[1]), "r"(a[2]), "r"(a[3]), "r"(b0), "r"(b1));
}

#define SB 136                         // bf16 elems per smem row (272B, conflict-free for ldmatrix)
#define ROWB (SB * 2)
#define A_HI_OFF 0
#define A_LO_OFF (128 * SB * 2)
#define B_HI_OFF (2 * 128 * SB * 2)
#define B_LO_OFF (3 * 128 * SB * 2)
#define SMEM_GEMM (4 * 128 * SB * 2)   // 139264 B

template <bool RELU_IN>
__global__ void __launch_bounds__(256, 1) k_gemm_bf16(const float* __restrict__ X,
                                                      const uint16_t* __restrict__ WH,
                                                      const uint16_t* __restrict__ WL,
                                                      const float* __restrict__ dis,
                                                      float* __restrict__ G, int M) {
    extern __shared__ char smem[];
    const uint32_t sbase = smem_u32(smem);
    const int t = threadIdx.x;
    const int wid = t >> 5, lane = t & 31;
    const int gid = lane >> 2, tg = lane & 3;
    const int wm = wid >> 1, wn = wid & 1;
    const int row0 = blockIdx.x * 128;

    // load A (fp32 -> relu -> hi/lo split) and B (pre-split) into smem
    for (int idx = t; idx < 4096; idx += 256) {   // 128 rows x 32 groups of 4
        int row = idx >> 5, q = (idx & 31) * 4;
        int gr = row0 + row; if (gr >= M) gr = M - 1;
        float4 v = *(const float4*)&X[(size_t)gr * DD + q];
        if (RELU_IN) {
            v.x = fmaxf(v.x, 0.0f); v.y = fmaxf(v.y, 0.0f);
            v.z = fmaxf(v.z, 0.0f); v.w = fmaxf(v.w, 0.0f);
        }
        __nv_bfloat16 h0 = __float2bfloat16_rn(v.x);
        __nv_bfloat16 h1 = __float2bfloat16_rn(v.y);
        __nv_bfloat16 h2 = __float2bfloat16_rn(v.z);
        __nv_bfloat16 h3 = __float2bfloat16_rn(v.w);
        __nv_bfloat16 l0 = __float2bfloat16_rn(v.x - __bfloat162float(h0));
        __nv_bfloat16 l1 = __float2bfloat16_rn(v.y - __bfloat162float(h1));
        __nv_bfloat16 l2 = __float2bfloat16_rn(v.z - __bfloat162float(h2));
        __nv_bfloat16 l3 = __float2bfloat16_rn(v.w - __bfloat162float(h3));
        uint2 hp, lp;
        hp.x = ((uint32_t)__bfloat16_as_ushort(h1) << 16) | __bfloat16_as_ushort(h0);
        hp.y = ((uint32_t)__bfloat16_as_ushort(h3) << 16) | __bfloat16_as_ushort(h2);
        lp.x = ((uint32_t)__bfloat16_as_ushort(l1) << 16) | __bfloat16_as_ushort(l0);
        lp.y = ((uint32_t)__bfloat16_as_ushort(l3) << 16) | __bfloat16_as_ushort(l2);
        *(uint2*)(smem + A_HI_OFF + (row * SB + q) * 2) = hp;
        *(uint2*)(smem + A_LO_OFF + (row * SB + q) * 2) = lp;
        uint2 wh = *(const uint2*)&WH[row * DD + q];
        uint2 wl = *(const uint2*)&WL[row * DD + q];
        *(uint2*)(smem + B_HI_OFF + (row * SB + q) * 2) = wh;
        *(uint2*)(smem + B_LO_OFF + (row * SB + q) * 2) = wl;
    }
    __syncthreads();

    float c[2][8][4];
#pragma unroll
    for (int mi = 0; mi < 2; mi++)
#pragma unroll
        for (int ni = 0; ni < 8; ni++)
#pragma unroll
            for (int q = 0; q < 4; q++) c[mi][ni][q] = 0.0f;

    // per-lane ldmatrix addressing
    const int a_r = wm * 32 + (lane & 15);
    const uint32_t a_koff = ((lane >> 4) & 1) * 16;
    const int b_r = wn * 64 + (lane & 7) + ((lane & 16) ? 8 : 0);
    const uint32_t b_koff = (lane & 8) ? 16 : 0;

#pragma unroll
    for (int ks = 0; ks < 8; ks++) {
        const uint32_t kb = ks * 32;   // 16 bf16 = 32 bytes per k-tile
        uint32_t ah[2][4], al[2][4];
#pragma unroll
        for (int mi = 0; mi < 2; mi++) {
            uint32_t ad = sbase + (uint32_t)((a_r + mi * 16) * ROWB) + a_koff + kb;
            ldsm4(ah[mi], ad + A_HI_OFF);
            ldsm4(al[mi], ad + A_LO_OFF);
        }
#pragma unroll
        for (int p = 0; p < 4; p++) {
            uint32_t bd = sbase + (uint32_t)((b_r + p * 16) * ROWB) + b_koff + kb;
            uint32_t bh[4], bl[4];
            ldsm4(bh, bd + B_HI_OFF);
            ldsm4(bl, bd + B_LO_OFF);
#pragma unroll
            for (int sub = 0; sub < 2; sub++) {
                int ni = p * 2 + sub;
                uint32_t b0h = bh[sub * 2], b1h = bh[sub * 2 + 1];
                uint32_t b0l = bl[sub * 2], b1l = bl[sub * 2 + 1];
#pragma unroll
                for (int mi = 0; mi < 2; mi++) {
                    mma_bf16(c[mi][ni], ah[mi], b0h, b1h);   // hi*hi
                    mma_bf16(c[mi][ni], ah[mi], b0l, b1l);   // hi*lo
                    mma_bf16(c[mi][ni], al[mi], b0h, b1h);   // lo*hi
                }
            }
        }
    }

    // epilogue: scale rows by dis and store
#pragma unroll
    for (int mi = 0; mi < 2; mi++) {
        int r0g = row0 + wm * 32 + mi * 16 + gid;
        int r1g = r0g + 8;
        float s0 = (r0g < M) ? dis[r0g] : 0.0f;
        float s1 = (r1g < M) ? dis[r1g] : 0.0f;
#pragma unroll
        for (int ni = 0; ni < 8; ni++) {
            int cg = wn * 64 + ni * 8 + tg * 2;
            if (r0g < M) {
                float2 v0 = make_float2(c[mi][ni][0] * s0, c[mi][ni][1] * s0);
                *(float2*)&G[(size_t)r0g * DD + cg] = v0;
            }
            if (r1g < M) {
                float2 v1 = make_float2(c[mi][ni][2] * s1, c[mi][ni][3] * s1);
                *(float2*)&G[(size_t)r1g * DD + cg] = v1;
            }
        }
    }
}

// ---------------- aggregation: out[i] = dis[i]*(g[i] + sum_{s in N(i)} g[s]) + b ----------------
__global__ void k_aggregate(const float* __restrict__ g, const float* __restrict__ dis,
                            const float* __restrict__ bias, const int* __restrict__ rp,
                            const int* __restrict__ col, float* __restrict__ out, int n) {
    int node = (blockIdx.x * blockDim.x + threadIdx.x) >> 5;
    int lane = threadIdx.x & 31;
    if (node >= n) return;

    const int c = lane * 4;
    int beg = rp[node];
    int end = rp[node + 1];

    float4 a0 = *(const float4*)&g[(size_t)node * DD + c];
    float4 a1 = make_float4(0.f, 0.f, 0.f, 0.f);

    int e = beg;
    for (; e + 4 <= end; e += 4) {
        int s0 = __ldg(&col[e + 0]);
        int s1 = __ldg(&col[e + 1]);
        int s2 = __ldg(&col[e + 2]);
        int s3 = __ldg(&col[e + 3]);
        float4 v0 = *(const float4*)&g[(size_t)s0 * DD + c];
        float4 v1 = *(const float4*)&g[(size_t)s1 * DD + c];
        float4 v2 = *(const float4*)&g[(size_t)s2 * DD + c];
        float4 v3 = *(const float4*)&g[(size_t)s3 * DD + c];
        a0.x += v0.x; a0.y += v0.y; a0.z += v0.z; a0.w += v0.w;
        a1.x += v1.x; a1.y += v1.y; a1.z += v1.z; a1.w += v1.w;
        a0.x += v2.x; a0.y += v2.y; a0.z += v2.z; a0.w += v2.w;
        a1.x += v3.x; a1.y += v3.y; a1.z += v3.z; a1.w += v3.w;
    }
    for (; e < end; e++) {
        int s = __ldg(&col[e]);
        float4 v = *(const float4*)&g[(size_t)s * DD + c];
        a0.x += v.x; a0.y += v.y; a0.z += v.z; a0.w += v.w;
    }

    float di = dis[node];
    const float4 bb = *(const float4*)&bias[c];
    float4 r;
    r.x = (a0.x + a1.x) * di + bb.x;
    r.y = (a0.y + a1.y) * di + bb.y;
    r.z = (a0.z + a1.z) * di + bb.z;
    r.w = (a0.w + a1.w) * di + bb.w;
    *(float4*)&out[(size_t)node * DD + c] = r;
}

// ---------------- orchestration ----------------
static void run_layer(const float* X, const uint16_t* WH, const uint16_t* WL, const float* b,
                      const float* dis, const int* rp, const int* col,
                      float* g, float* out, bool relu_in) {
    const int gemm_blocks = (NN + 127) / 128;
    if (relu_in)
        k_gemm_bf16<true><<<gemm_blocks, 256, SMEM_GEMM>>>(X, WH, WL, dis, g, NN);
    else
        k_gemm_bf16<false><<<gemm_blocks, 256, SMEM_GEMM>>>(X, WH, WL, dis, g, NN);

    const long long threads = (long long)NN * 32;
    k_aggregate<<<(int)((threads + 255) / 256), 256>>>(g, dis, b, rp, col, out, NN);
}

extern "C" void kernel_launch(void* const* d_in, const int* in_sizes, int n_in,
                              void* d_out, int out_size) {
    const float* x      = (const float*)d_in[0];
    const float* W_role = (const float*)d_in[1];
    const float* b_role = (const float*)d_in[2];
    const float* W2     = (const float*)d_in[3];
    const float* b2     = (const float*)d_in[4];
    const float* W1     = (const float*)d_in[5];
    const float* b1     = (const float*)d_in[6];
    const int* ei_norm  = (const int*)d_in[7];
    const int* ei_role  = (const int*)d_in[8];

    float *h, *o, *dis_role, *dis_norm;
    uint16_t *wthi, *wtlo;
    int *cnt, *cur, *bsum, *boff, *rp_role, *rp_norm, *col_role, *col_norm;
    cudaGetSymbolAddress((void**)&h, g_h);
    cudaGetSymbolAddress((void**)&o, g_o);
    cudaGetSymbolAddress((void**)&wthi, g_wthi);
    cudaGetSymbolAddress((void**)&wtlo, g_wtlo);
    cudaGetSymbolAddress((void**)&dis_role, g_dis_role);
    cudaGetSymbolAddress((void**)&dis_norm, g_dis_norm);
    cudaGetSymbolAddress((void**)&cnt, g_cnt);
    cudaGetSymbolAddress((void**)&cur, g_cur);
    cudaGetSymbolAddress((void**)&bsum, g_bsum);
    cudaGetSymbolAddress((void**)&boff, g_boff);
    cudaGetSymbolAddress((void**)&rp_role, g_rp_role);
    cudaGetSymbolAddress((void**)&rp_norm, g_rp_norm);
    cudaGetSymbolAddress((void**)&col_role, g_col_role);
    cudaGetSymbolAddress((void**)&col_norm, g_col_norm);

    static bool attr_set = false;
    if (!attr_set) {
        cudaFuncSetAttribute(k_gemm_bf16<true>,  cudaFuncAttributeMaxDynamicSharedMemorySize, SMEM_GEMM);
        cudaFuncSetAttribute(k_gemm_bf16<false>, cudaFuncAttributeMaxDynamicSharedMemorySize, SMEM_GEMM);
        attr_set = true;
    }

    const int* src_norm = ei_norm;
    const int* dst_norm = ei_norm + NE;
    const int* src_role = ei_role;
    const int* dst_role = ei_role + NE;

    // transposed + pre-split weights: order = [W_role, W2, W1]
    {
        dim3 tb(32, 8), tg(4, 4, 3);
        k_transpose3<<<tg, tb>>>(W_role, W2, W1, wthi, wtlo);
    }

    // CSR build, both graphs per kernel (graph = blockIdx.y; 0 = role, 1 = normal)
    {
        k_zero2<<<(2 * NN + 255) / 256, 256>>>(cnt, 2 * NN);
        dim3 ge((NE + 255) / 256, 2);
        k_hist2<<<ge, 256>>>(dst_role, dst_norm, cnt);
        dim3 gs(SCAN_NB, 2);
        k_scan1<<<gs, SCAN_B>>>(cnt, rp_role, rp_norm, cur, dis_role, dis_norm, bsum);
        k_scan2<<<2, 64>>>(bsum, boff);
        k_scan3<<<gs, SCAN_B>>>(rp_role, rp_norm, cur, boff);
        k_fill2<<<ge, 256>>>(src_role, dst_role, src_norm, dst_norm, cur, col_role, col_norm);
    }

    // layer 1: role graph
    run_layer(x, wthi + 0 * DD * DD, wtlo + 0 * DD * DD, b_role, dis_role, rp_role, col_role, h, o, false);
    // layer 2: normal graph (relu on layer-1 output applied at GEMM input)
    run_layer(o, wthi + 1 * DD * DD, wtlo + 1 * DD * DD, b2, dis_norm, rp_norm, col_norm, h, o, true);
    // layer 3: normal graph, final output
    run_layer(o, wthi + 2 * DD * DD, wtlo + 2 * DD * DD, b1, dis_norm, rp_norm, col_norm, h, (float*)d_out, true);
}